// round 4
// baseline (speedup 1.0000x reference)
#include <cuda_runtime.h>

#define HID 16
#define MAXN 4096
#define WSET 336  // floats per weight set; 16B multiple

__device__ float4 g_pifrac[MAXN];
__device__ float  g_C[9];      // cell / pi
__device__ float  g_invrs;

__device__ __forceinline__ float tanh_ap(float x) {
    float y;
    asm("tanh.approx.f32 %0, %1;" : "=f"(y) : "f"(x));
    return y;
}

__global__ void prep_kernel(const float* __restrict__ x, const float* __restrict__ cell,
                            float* __restrict__ out, int n) {
    __shared__ float sinv[9];
    const float PI = 3.14159265358979323846f;
    if (threadIdx.x == 0) {
        float c[9];
#pragma unroll
        for (int i = 0; i < 9; i++) c[i] = cell[i];
        float det = c[0]*(c[4]*c[8]-c[5]*c[7])
                  - c[1]*(c[3]*c[8]-c[5]*c[6])
                  + c[2]*(c[3]*c[7]-c[4]*c[6]);
        float id = 1.0f / det;
        sinv[0]=(c[4]*c[8]-c[5]*c[7])*id; sinv[1]=(c[2]*c[7]-c[1]*c[8])*id; sinv[2]=(c[1]*c[5]-c[2]*c[4])*id;
        sinv[3]=(c[5]*c[6]-c[3]*c[8])*id; sinv[4]=(c[0]*c[8]-c[2]*c[6])*id; sinv[5]=(c[2]*c[3]-c[0]*c[5])*id;
        sinv[6]=(c[3]*c[7]-c[4]*c[6])*id; sinv[7]=(c[1]*c[6]-c[0]*c[7])*id; sinv[8]=(c[0]*c[4]-c[1]*c[3])*id;
        float volpp = fabsf(det) / (float)n;
        g_invrs = cbrtf(4.0f * PI / (3.0f * volpp));   // 1/rs
#pragma unroll
        for (int i = 0; i < 9; i++) g_C[i] = c[i] / PI;
    }
    __syncthreads();
    for (int i = threadIdx.x; i < n; i += blockDim.x) {
        float x0 = x[3*i+0], x1 = x[3*i+1], x2 = x[3*i+2];
        float f0 = x0*sinv[0] + x1*sinv[3] + x2*sinv[6];
        float f1 = x0*sinv[1] + x1*sinv[4] + x2*sinv[7];
        float f2 = x0*sinv[2] + x1*sinv[5] + x2*sinv[8];
        g_pifrac[i] = make_float4(PI*f0, PI*f1, PI*f2, 0.f);
        out[3*i+0] = x0; out[3*i+1] = x1; out[3*i+2] = x2;
    }
}

// Core pair evaluation: layer-1 fused into the k-loop (no h[] array),
// weight base pointer fixed for the whole loop.
__device__ __forceinline__ void pair_loop(
    const float* __restrict__ wb, const float4* __restrict__ wb4,
    float4 pfj, int j, int ibeg, int iend, int lane,
    float C00, float C01, float C02, float C10, float C11, float C12,
    float C20, float C21, float C22, float invrs,
    float& acc0, float& acc1, float& acc2)
{
    for (int i = ibeg + lane; i < iend; i += 32) {
        float4 pfi = g_pifrac[i];
        float s0 = __sinf(pfj.x - pfi.x);
        float s1 = __sinf(pfj.y - pfi.y);
        float s2 = __sinf(pfj.z - pfi.z);
        float v0 = s0*C00 + s1*C10 + s2*C20;
        float v1 = s0*C01 + s1*C11 + s2*C21;
        float v2 = s0*C02 + s1*C12 + s2*C22;
        float s  = sqrtf(v0*v0 + v1*v1 + v2*v2) * invrs;

        // g init from b2
        float g[16];
#pragma unroll
        for (int h4 = 0; h4 < 4; h4++) {
            float4 b2v = wb4[72 + h4];
            g[4*h4+0] = b2v.x; g[4*h4+1] = b2v.y; g[4*h4+2] = b2v.z; g[4*h4+3] = b2v.w;
        }
        // fused layer1 + layer2
#pragma unroll
        for (int k4 = 0; k4 < 4; k4++) {
            float4 w1v = wb4[k4], b1v = wb4[4 + k4];
            float hk0 = tanh_ap(fmaf(s, w1v.x, b1v.x));
            float hk1 = tanh_ap(fmaf(s, w1v.y, b1v.y));
            float hk2 = tanh_ap(fmaf(s, w1v.z, b1v.z));
            float hk3 = tanh_ap(fmaf(s, w1v.w, b1v.w));
#pragma unroll
            for (int kk = 0; kk < 4; kk++) {
                float hk = kk == 0 ? hk0 : (kk == 1 ? hk1 : (kk == 2 ? hk2 : hk3));
                int k = 4*k4 + kk;
                float4 r0 = wb4[8 + 4*k], r1 = wb4[9 + 4*k], r2 = wb4[10 + 4*k], r3 = wb4[11 + 4*k];
                g[0]  = fmaf(hk, r0.x, g[0]);  g[1]  = fmaf(hk, r0.y, g[1]);
                g[2]  = fmaf(hk, r0.z, g[2]);  g[3]  = fmaf(hk, r0.w, g[3]);
                g[4]  = fmaf(hk, r1.x, g[4]);  g[5]  = fmaf(hk, r1.y, g[5]);
                g[6]  = fmaf(hk, r1.z, g[6]);  g[7]  = fmaf(hk, r1.w, g[7]);
                g[8]  = fmaf(hk, r2.x, g[8]);  g[9]  = fmaf(hk, r2.y, g[9]);
                g[10] = fmaf(hk, r2.z, g[10]); g[11] = fmaf(hk, r2.w, g[11]);
                g[12] = fmaf(hk, r3.x, g[12]); g[13] = fmaf(hk, r3.y, g[13]);
                g[14] = fmaf(hk, r3.z, g[14]); g[15] = fmaf(hk, r3.w, g[15]);
            }
        }
        // layer 3
        float ea = wb[320], eb = 0.f;
#pragma unroll
        for (int h4 = 0; h4 < 4; h4++) {
            float4 w3v = wb4[76 + h4];
            ea = fmaf(tanh_ap(g[4*h4+0]), w3v.x, ea);
            eb = fmaf(tanh_ap(g[4*h4+1]), w3v.y, eb);
            ea = fmaf(tanh_ap(g[4*h4+2]), w3v.z, ea);
            eb = fmaf(tanh_ap(g[4*h4+3]), w3v.w, eb);
        }
        float eta = ea + eb;
        if (i == j) eta = 0.f;
        acc0 = fmaf(eta, v0, acc0);
        acc1 = fmaf(eta, v1, acc1);
        acc2 = fmaf(eta, v2, acc2);
    }
}

// One warp handles (j, quarter-chunk of i).
__global__ void __launch_bounds__(256, 3) pair_kernel(
    const float* __restrict__ Wp1, const float* __restrict__ bp1,
    const float* __restrict__ Wp2, const float* __restrict__ bp2,
    const float* __restrict__ Wp3, const float* __restrict__ bp3,
    const float* __restrict__ Wa1, const float* __restrict__ ba1,
    const float* __restrict__ Wa2, const float* __restrict__ ba2,
    const float* __restrict__ Wa3, const float* __restrict__ ba3,
    const int* __restrict__ n_up_ptr, float* __restrict__ out, int n)
{
    __shared__ __align__(16) float sw[2 * WSET];
    // layout per set: w1[16] @0, b1[16] @16, w2[256] @32 ([k][h] row-major),
    //                 b2[16] @288, w3[16] @304, b3 @320
    int tid = threadIdx.x;
    if (tid < 16) {
        sw[tid]          = Wp1[tid];
        sw[16 + tid]     = bp1[tid];
        sw[288 + tid]    = bp2[tid];
        sw[304 + tid]    = Wp3[tid];
        sw[WSET + tid]       = Wa1[tid];
        sw[WSET + 16 + tid]  = ba1[tid];
        sw[WSET + 288 + tid] = ba2[tid];
        sw[WSET + 304 + tid] = Wa3[tid];
    }
    if (tid == 16) { sw[320] = bp3[0]; sw[WSET + 320] = ba3[0]; }
    for (int t = tid; t < 256; t += 256) {
        sw[32 + t]        = Wp2[t];
        sw[WSET + 32 + t] = Wa2[t];
    }
    __syncthreads();

    int w    = (blockIdx.x * 256 + tid) >> 5;
    int lane = tid & 31;
    int j    = w >> 2;
    if (j >= n) return;
    int csz  = (n + 3) >> 2;
    int ibeg = (w & 3) * csz;
    int iend = ibeg + csz; if (iend > n) iend = n;
    if (ibeg >= iend) return;

    int  n_up = *n_up_ptr;
    bool j_up = (j < n_up);

    float4 pfj   = g_pifrac[j];
    float  invrs = g_invrs;
    float C00=g_C[0], C01=g_C[1], C02=g_C[2];
    float C10=g_C[3], C11=g_C[4], C12=g_C[5];
    float C20=g_C[6], C21=g_C[7], C22=g_C[8];

    float acc0 = 0.f, acc1 = 0.f, acc2 = 0.f;

    bool uni = ((ibeg < n_up) == ((iend - 1) < n_up));
    if (uni) {
        const float* wb = sw + (((ibeg < n_up) == j_up) ? 0 : WSET);
        pair_loop(wb, (const float4*)wb, pfj, j, ibeg, iend, lane,
                  C00, C01, C02, C10, C11, C12, C20, C21, C22, invrs,
                  acc0, acc1, acc2);
    } else {
        // straddling chunk: split at n_up so each sub-range is uniform
        int mid = n_up;
        const float* wbL = sw + ((true  == j_up) ? 0 : WSET);  // i < n_up -> up spin
        const float* wbR = sw + ((false == j_up) ? 0 : WSET);  // i >= n_up
        // left part [ibeg, mid): lanes continue their own stride, so recompute
        // per-range with matching lane offset
        int lbeg = ibeg, lend = mid < iend ? mid : iend;
        pair_loop(wbL, (const float4*)wbL, pfj, j, lbeg, lend, lane,
                  C00, C01, C02, C10, C11, C12, C20, C21, C22, invrs,
                  acc0, acc1, acc2);
        int rbeg = mid > ibeg ? mid : ibeg, rend = iend;
        if (rbeg < rend)
            pair_loop(wbR, (const float4*)wbR, pfj, j, rbeg, rend, lane,
                      C00, C01, C02, C10, C11, C12, C20, C21, C22, invrs,
                      acc0, acc1, acc2);
    }

#pragma unroll
    for (int o = 16; o > 0; o >>= 1) {
        acc0 += __shfl_xor_sync(0xffffffffu, acc0, o);
        acc1 += __shfl_xor_sync(0xffffffffu, acc1, o);
        acc2 += __shfl_xor_sync(0xffffffffu, acc2, o);
    }
    if (lane == 0) {
        atomicAdd(&out[3*j+0], acc0);
        atomicAdd(&out[3*j+1], acc1);
        atomicAdd(&out[3*j+2], acc2);
    }
}

extern "C" void kernel_launch(void* const* d_in, const int* in_sizes, int n_in,
                              void* d_out, int out_size) {
    const float* x    = (const float*)d_in[0];
    const float* cell = (const float*)d_in[1];
    const float* Wp1  = (const float*)d_in[2];
    const float* bp1  = (const float*)d_in[3];
    const float* Wp2  = (const float*)d_in[4];
    const float* bp2  = (const float*)d_in[5];
    const float* Wp3  = (const float*)d_in[6];
    const float* bp3  = (const float*)d_in[7];
    const float* Wa1  = (const float*)d_in[8];
    const float* ba1  = (const float*)d_in[9];
    const float* Wa2  = (const float*)d_in[10];
    const float* ba2  = (const float*)d_in[11];
    const float* Wa3  = (const float*)d_in[12];
    const float* ba3  = (const float*)d_in[13];
    const int*   n_up = (const int*)d_in[14];
    float* out = (float*)d_out;

    int n = in_sizes[0] / 3;
    prep_kernel<<<1, 256>>>(x, cell, out, n);
    int nwarps = n * 4;                       // (j, quarter) per warp
    int blocks = (nwarps * 32 + 255) / 256;
    pair_kernel<<<blocks, 256>>>(Wp1, bp1, Wp2, bp2, Wp3, bp3,
                                 Wa1, ba1, Wa2, ba2, Wa3, ba3,
                                 n_up, out, n);
}

// round 5
// speedup vs baseline: 6.5570x; 6.5570x over previous
#include <cuda_runtime.h>

#define HID 16
#define MAXN 4096
#define WSET 336  // floats per weight set; 336*4=1344B, 16B multiple
#define CHUNKS 8

__device__ float4 g_pifrac[MAXN];
__device__ float  g_C[9];      // cell / pi
__device__ float  g_invrs;

__device__ __forceinline__ float tanh_ap(float x) {
    float y;
    asm("tanh.approx.f32 %0, %1;" : "=f"(y) : "f"(x));
    return y;
}

__global__ void prep_kernel(const float* __restrict__ x, const float* __restrict__ cell,
                            float* __restrict__ out, int n) {
    __shared__ float sinv[9];
    const float PI = 3.14159265358979323846f;
    if (threadIdx.x == 0) {
        float c[9];
#pragma unroll
        for (int i = 0; i < 9; i++) c[i] = cell[i];
        float det = c[0]*(c[4]*c[8]-c[5]*c[7])
                  - c[1]*(c[3]*c[8]-c[5]*c[6])
                  + c[2]*(c[3]*c[7]-c[4]*c[6]);
        float id = 1.0f / det;
        sinv[0]=(c[4]*c[8]-c[5]*c[7])*id; sinv[1]=(c[2]*c[7]-c[1]*c[8])*id; sinv[2]=(c[1]*c[5]-c[2]*c[4])*id;
        sinv[3]=(c[5]*c[6]-c[3]*c[8])*id; sinv[4]=(c[0]*c[8]-c[2]*c[6])*id; sinv[5]=(c[2]*c[3]-c[0]*c[5])*id;
        sinv[6]=(c[3]*c[7]-c[4]*c[6])*id; sinv[7]=(c[1]*c[6]-c[0]*c[7])*id; sinv[8]=(c[0]*c[4]-c[1]*c[3])*id;
        float volpp = fabsf(det) / (float)n;
        g_invrs = cbrtf(4.0f * PI / (3.0f * volpp));   // 1/rs
#pragma unroll
        for (int i = 0; i < 9; i++) g_C[i] = c[i] / PI;
    }
    __syncthreads();
    for (int i = threadIdx.x; i < n; i += blockDim.x) {
        float x0 = x[3*i+0], x1 = x[3*i+1], x2 = x[3*i+2];
        float f0 = x0*sinv[0] + x1*sinv[3] + x2*sinv[6];
        float f1 = x0*sinv[1] + x1*sinv[4] + x2*sinv[7];
        float f2 = x0*sinv[2] + x1*sinv[5] + x2*sinv[8];
        g_pifrac[i] = make_float4(PI*f0, PI*f1, PI*f2, 0.f);
        out[3*i+0] = x0; out[3*i+1] = x1; out[3*i+2] = x2;
    }
}

// One warp handles (j, 1/CHUNKS slice of i). Round-1 proven body (78 regs).
__global__ void __launch_bounds__(256) pair_kernel(
    const float* __restrict__ Wp1, const float* __restrict__ bp1,
    const float* __restrict__ Wp2, const float* __restrict__ bp2,
    const float* __restrict__ Wp3, const float* __restrict__ bp3,
    const float* __restrict__ Wa1, const float* __restrict__ ba1,
    const float* __restrict__ Wa2, const float* __restrict__ ba2,
    const float* __restrict__ Wa3, const float* __restrict__ ba3,
    const int* __restrict__ n_up_ptr, float* __restrict__ out, int n)
{
    __shared__ __align__(16) float sw[2 * WSET];
    // layout per set: w1[16] @0, b1[16] @16, w2[256] @32 (row-major [k][h]),
    //                 b2[16] @288, w3[16] @304, b3 @320
    int tid = threadIdx.x;
    if (tid < 16) {
        sw[tid]          = Wp1[tid];
        sw[16 + tid]     = bp1[tid];
        sw[288 + tid]    = bp2[tid];
        sw[304 + tid]    = Wp3[tid];
        sw[WSET + tid]       = Wa1[tid];
        sw[WSET + 16 + tid]  = ba1[tid];
        sw[WSET + 288 + tid] = ba2[tid];
        sw[WSET + 304 + tid] = Wa3[tid];
    }
    if (tid == 16) { sw[320] = bp3[0]; sw[WSET + 320] = ba3[0]; }
    for (int t = tid; t < 256; t += 256) {
        sw[32 + t]        = Wp2[t];
        sw[WSET + 32 + t] = Wa2[t];
    }
    __syncthreads();

    int w    = (blockIdx.x * 256 + tid) >> 5;
    int lane = tid & 31;
    int j    = w >> 3;                 // CHUNKS=8 -> j = w/8
    if (j >= n) return;
    int csz  = (n + CHUNKS - 1) / CHUNKS;
    int ibeg = (w & (CHUNKS - 1)) * csz;
    int iend = ibeg + csz; if (iend > n) iend = n;
    if (ibeg >= iend) return;

    int  n_up = *n_up_ptr;
    bool j_up = (j < n_up);

    float4 pfj   = g_pifrac[j];
    float  invrs = g_invrs;
    float C00=g_C[0], C01=g_C[1], C02=g_C[2];
    float C10=g_C[3], C11=g_C[4], C12=g_C[5];
    float C20=g_C[6], C21=g_C[7], C22=g_C[8];

    float acc0 = 0.f, acc1 = 0.f, acc2 = 0.f;

    for (int i = ibeg + lane; i < iend; i += 32) {
        float4 pfi = g_pifrac[i];
        float s0 = __sinf(pfj.x - pfi.x);
        float s1 = __sinf(pfj.y - pfi.y);
        float s2 = __sinf(pfj.z - pfi.z);
        // v = -d_hsin[i,j]
        float v0 = s0*C00 + s1*C10 + s2*C20;
        float v1 = s0*C01 + s1*C11 + s2*C21;
        float v2 = s0*C02 + s1*C12 + s2*C22;
        float q  = v0*v0 + v1*v1 + v2*v2;
        float s  = sqrtf(q) * invrs;

        const float*  wb  = sw + (((i < n_up) == j_up) ? 0 : WSET);
        const float4* wb4 = (const float4*)wb;

        // layer 1: h = tanh(s*w1 + b1)
        float h[16];
#pragma unroll
        for (int k4 = 0; k4 < 4; k4++) {
            float4 w1v = wb4[k4], b1v = wb4[4 + k4];
            h[4*k4+0] = tanh_ap(fmaf(s, w1v.x, b1v.x));
            h[4*k4+1] = tanh_ap(fmaf(s, w1v.y, b1v.y));
            h[4*k4+2] = tanh_ap(fmaf(s, w1v.z, b1v.z));
            h[4*k4+3] = tanh_ap(fmaf(s, w1v.w, b1v.w));
        }
        // layer 2: g = tanh(h @ W2 + b2)
        float g[16];
#pragma unroll
        for (int h4 = 0; h4 < 4; h4++) {
            float4 b2v = wb4[72 + h4];
            g[4*h4+0] = b2v.x; g[4*h4+1] = b2v.y; g[4*h4+2] = b2v.z; g[4*h4+3] = b2v.w;
        }
#pragma unroll
        for (int k = 0; k < 16; k++) {
            float hk = h[k];
            float4 r0 = wb4[8 + 4*k], r1 = wb4[9 + 4*k], r2 = wb4[10 + 4*k], r3 = wb4[11 + 4*k];
            g[0]  = fmaf(hk, r0.x, g[0]);  g[1]  = fmaf(hk, r0.y, g[1]);
            g[2]  = fmaf(hk, r0.z, g[2]);  g[3]  = fmaf(hk, r0.w, g[3]);
            g[4]  = fmaf(hk, r1.x, g[4]);  g[5]  = fmaf(hk, r1.y, g[5]);
            g[6]  = fmaf(hk, r1.z, g[6]);  g[7]  = fmaf(hk, r1.w, g[7]);
            g[8]  = fmaf(hk, r2.x, g[8]);  g[9]  = fmaf(hk, r2.y, g[9]);
            g[10] = fmaf(hk, r2.z, g[10]); g[11] = fmaf(hk, r2.w, g[11]);
            g[12] = fmaf(hk, r3.x, g[12]); g[13] = fmaf(hk, r3.y, g[13]);
            g[14] = fmaf(hk, r3.z, g[14]); g[15] = fmaf(hk, r3.w, g[15]);
        }
        // layer 3: eta = tanh(g) @ w3 + b3
        float ea = wb[320], eb = 0.f;
#pragma unroll
        for (int h4 = 0; h4 < 4; h4++) {
            float4 w3v = wb4[76 + h4];
            ea = fmaf(tanh_ap(g[4*h4+0]), w3v.x, ea);
            eb = fmaf(tanh_ap(g[4*h4+1]), w3v.y, eb);
            ea = fmaf(tanh_ap(g[4*h4+2]), w3v.z, ea);
            eb = fmaf(tanh_ap(g[4*h4+3]), w3v.w, eb);
        }
        float eta = ea + eb;
        if (i == j) eta = 0.f;
        acc0 = fmaf(eta, v0, acc0);
        acc1 = fmaf(eta, v1, acc1);
        acc2 = fmaf(eta, v2, acc2);
    }

#pragma unroll
    for (int o = 16; o > 0; o >>= 1) {
        acc0 += __shfl_xor_sync(0xffffffffu, acc0, o);
        acc1 += __shfl_xor_sync(0xffffffffu, acc1, o);
        acc2 += __shfl_xor_sync(0xffffffffu, acc2, o);
    }
    if (lane == 0) {
        atomicAdd(&out[3*j+0], acc0);
        atomicAdd(&out[3*j+1], acc1);
        atomicAdd(&out[3*j+2], acc2);
    }
}

extern "C" void kernel_launch(void* const* d_in, const int* in_sizes, int n_in,
                              void* d_out, int out_size) {
    const float* x    = (const float*)d_in[0];
    const float* cell = (const float*)d_in[1];
    const float* Wp1  = (const float*)d_in[2];
    const float* bp1  = (const float*)d_in[3];
    const float* Wp2  = (const float*)d_in[4];
    const float* bp2  = (const float*)d_in[5];
    const float* Wp3  = (const float*)d_in[6];
    const float* bp3  = (const float*)d_in[7];
    const float* Wa1  = (const float*)d_in[8];
    const float* ba1  = (const float*)d_in[9];
    const float* Wa2  = (const float*)d_in[10];
    const float* ba2  = (const float*)d_in[11];
    const float* Wa3  = (const float*)d_in[12];
    const float* ba3  = (const float*)d_in[13];
    const int*   n_up = (const int*)d_in[14];
    float* out = (float*)d_out;

    int n = in_sizes[0] / 3;
    prep_kernel<<<1, 256>>>(x, cell, out, n);
    int nwarps = n * CHUNKS;                  // (j, chunk) per warp
    int blocks = (nwarps * 32 + 255) / 256;
    pair_kernel<<<blocks, 256>>>(Wp1, bp1, Wp2, bp2, Wp3, bp3,
                                 Wa1, ba1, Wa2, ba2, Wa3, ba3,
                                 n_up, out, n);
}